// round 16
// baseline (speedup 1.0000x reference)
#include <cuda_runtime.h>
#include <cuda_fp16.h>
#include <cstdint>

// ---------------- problem constants ----------------
#define BB    8
#define TT    2048
#define CCH   1024
#define BT    (BB*TT)          // 16384 rows
#define N3    (3*CCH)          // 3072
#define N4    (4*CCH)          // 4096
#define NCTA  296              // 148 SMs x 2 CTAs (persistent grid)

// ---------------- scratch (device globals, no allocation) ----------------
__device__ __half g_ln1h[(size_t)BT*CCH];
__device__ float  g_K  [(size_t)BT*CCH];
__device__ float  g_V  [(size_t)BT*CCH];
__device__ float  g_R  [(size_t)BT*CCH];
__device__ float  g_X1 [(size_t)BT*CCH];
__device__ float  g_XN [(size_t)BT*CCH];
__device__ __half g_XNh[(size_t)BT*CCH];
__device__ __half g_Hh [(size_t)BT*N4];
__device__ __half g_Wtm[(size_t)CCH*N3];   // transposed: (3C, C) half
__device__ __half g_Wcm[(size_t)CCH*N4];   // transposed: (4C, C) half
__device__ __half g_Wcp[(size_t)N4*CCH];   // transposed: (C, 4C) half

// ---------------- helpers ----------------
__device__ __forceinline__ float sigmoidf_(float z) {
    return 1.0f / (1.0f + __expf(-z));
}
__device__ __forceinline__ void cp16s(uint32_t dst, const void* src) {
    asm volatile("cp.async.cg.shared.global [%0], [%1], 16;\n"
                 :: "r"(dst), "l"(src) : "memory");
}
#define CP_COMMIT() asm volatile("cp.async.commit_group;\n" ::: "memory")
#define CP_WAIT(Ng) asm volatile("cp.async.wait_group %0;\n" :: "n"(Ng) : "memory")

__device__ __forceinline__ void mma_f16(float* c, const uint32_t* a, const uint32_t* b) {
    asm volatile(
        "mma.sync.aligned.m16n8k16.row.col.f32.f16.f16.f32 "
        "{%0,%1,%2,%3}, {%4,%5,%6,%7}, {%8,%9}, {%0,%1,%2,%3};"
        : "+f"(c[0]), "+f"(c[1]), "+f"(c[2]), "+f"(c[3])
        : "r"(a[0]), "r"(a[1]), "r"(a[2]), "r"(a[3]), "r"(b[0]), "r"(b[1]));
}
__device__ __forceinline__ void ldsm4(uint32_t& r0, uint32_t& r1,
                                      uint32_t& r2, uint32_t& r3, uint32_t a) {
    asm volatile("ldmatrix.sync.aligned.m8n8.x4.shared.b16 {%0,%1,%2,%3}, [%4];"
                 : "=r"(r0), "=r"(r1), "=r"(r2), "=r"(r3) : "r"(a));
}

// ---------------- transpose + fp16 convert (W K x N -> Wt N x K) ----------
__global__ void __launch_bounds__(256) transpose_h(const float* __restrict__ in,
                                                   __half* __restrict__ out,
                                                   int Kd, int Nd)
{
    __shared__ float tile[32][33];
    const int bx = blockIdx.x * 32;   // N
    const int by = blockIdx.y * 32;   // K
    const int tx = threadIdx.x, ty = threadIdx.y;
    #pragma unroll
    for (int i = 0; i < 32; i += 8)
        tile[ty + i][tx] = in[(size_t)(by + ty + i) * Nd + bx + tx];
    __syncthreads();
    #pragma unroll
    for (int i = 0; i < 32; i += 8)
        out[(size_t)(bx + ty + i) * Kd + by + tx] = __float2half_rn(tile[tx][ty + i]);
}

// ---------------- LayerNorm: half output (+ optional fp32 copy) -----------
__global__ void __launch_bounds__(256) ln_kernel(const float* __restrict__ x,
                                                 const float* __restrict__ g,
                                                 const float* __restrict__ b,
                                                 __half* __restrict__ outh,
                                                 float* __restrict__ outf)
{
    const int row  = blockIdx.x;
    const int tid  = threadIdx.x;
    const int lane = tid & 31, wid = tid >> 5;

    const float4* xr = (const float4*)(x + (size_t)row * CCH);
    float4 v = xr[tid];
    float s = v.x + v.y + v.z + v.w;
    float q = v.x*v.x + v.y*v.y + v.z*v.z + v.w*v.w;

    #pragma unroll
    for (int o = 16; o > 0; o >>= 1) {
        s += __shfl_xor_sync(0xffffffffu, s, o);
        q += __shfl_xor_sync(0xffffffffu, q, o);
    }
    __shared__ float sh_s[8], sh_q[8];
    if (lane == 0) { sh_s[wid] = s; sh_q[wid] = q; }
    __syncthreads();
    float S = 0.f, Q = 0.f;
    #pragma unroll
    for (int i = 0; i < 8; i++) { S += sh_s[i]; Q += sh_q[i]; }

    const float mean = S * (1.0f / CCH);
    float var = Q * (1.0f / CCH) - mean * mean;
    var = fmaxf(var, 0.0f);
    const float rstd = rsqrtf(var + 1e-5f);

    float4 gg = ((const float4*)g)[tid];
    float4 bb4 = ((const float4*)b)[tid];
    float4 o4;
    o4.x = (v.x - mean) * rstd * gg.x + bb4.x;
    o4.y = (v.y - mean) * rstd * gg.y + bb4.y;
    o4.z = (v.z - mean) * rstd * gg.z + bb4.z;
    o4.w = (v.w - mean) * rstd * gg.w + bb4.w;

    __half2 h0 = __floats2half2_rn(o4.x, o4.y);
    __half2 h1 = __floats2half2_rn(o4.z, o4.w);
    uint2 hh; hh.x = *(uint32_t*)&h0; hh.y = *(uint32_t*)&h1;
    ((uint2*)(outh + (size_t)row * CCH))[tid] = hh;
    if (outf) ((float4*)(outf + (size_t)row * CCH))[tid] = o4;
}

// ---------------- WKV scan: EXACT reference recurrence ----------------
// Reference recurrence in scaled parameterization (renorm every 8 steps),
// depth-8 register pipeline: step t+8's operands load while step t computes.
__global__ void __launch_bounds__(32) wkv_kernel(const float* __restrict__ td,
                                                 const float* __restrict__ tf,
                                                 const float* __restrict__ Kb,
                                                 const float* __restrict__ Vb,
                                                 const float* __restrict__ Rb,
                                                 const float* __restrict__ x,
                                                 float* __restrict__ X1,
                                                 float* __restrict__ state)
{
    const int bidx = blockIdx.x >> 5;
    const int c    = ((blockIdx.x & 31) << 5) + threadIdx.x;
    const float w = td[c], u = tf[c];
    const float E   = __expf(w);
    const float Eu  = __expf(u);
    const float eps = 1e-8f;

    const size_t base = (size_t)bidx * TT * CCH + c;

    float kb[8], vb[8], rb[8], xb[8];
    #pragma unroll
    for (int j = 0; j < 8; ++j) {
        const size_t i0 = base + (size_t)j * CCH;
        kb[j] = Kb[i0]; vb[j] = Vb[i0]; rb[j] = Rb[i0]; xb[j] = x[i0];
    }

    float sigma = kb[0];       // so ek(t=0) = 1 (matches bb after step 0)
    float aa = 0.0f, bt = 0.0f;
    size_t idx = base;

    for (int t0 = 0; t0 < TT; t0 += 8) {
        #pragma unroll
        for (int j = 0; j < 8; ++j) {
            const float kk = kb[j], vv = vb[j], rr = rb[j], xx = xb[j];
            if (t0 + j + 8 < TT) {
                const size_t ip = idx + (size_t)(8 * CCH);
                kb[j] = Kb[ip]; vb[j] = Vb[ip]; rb[j] = Rb[ip]; xb[j] = x[ip];
            }
            const float ek  = __expf(kk - sigma);   // off the carried chain
            const float eku = Eu * ek;
            const float mp = fmaxf(bt, eku);
            const float y  = fmaf(bt, aa, eku * vv) / fmaf(eps, mp, bt + eku);
            X1[idx] = xx + rr * y;
            const float Ebt = E * bt;
            const float m   = fmaxf(Ebt, ek);
            aa = fmaf(Ebt, aa, ek * vv) / m;
            bt = fmaf(eps, m, Ebt + ek);
            idx += CCH;
        }
        sigma += __logf(bt);    // renormalize window (t & 7) == 7
        bt = 1.0f;
    }
    state[((size_t)bidx * CCH + c) * 2 + 0] = aa;
    state[((size_t)bidx * CCH + c) * 2 + 1] = sigma;   // + log(1)
}

// ---------------- FP16 mma.sync GEMM, persistent CTAs -------------------
// C = A(MxK, row, half) @ Wt(NxK, row, half)^T ; fp32 accumulate.
// CTA tile: 128(M) x 128(N), BK=32, 256 thr, 8 warps (2x4), warp 64x32.
// 4-stage cp.async, one sync/k-tile, 2 CTAs/SM. Grid fixed at NCTA=296;
// each CTA loops over output tiles -> zero wave quantization.
#define GBK    32
#define ROWB   80                      // bytes per smem row (40 halves)
#define STGA   (128*ROWB)              // 10240 B
#define NSTG   4
#define BN     128
#define STG_   (STGA + BN*ROWB)        // 20480 B
#define SMEM_TOT (NSTG*STG_)           // 81920 B

#define LOADSTAGE(s_, kt_) do {                                               \
    uint32_t ab_ = smem + (uint32_t)(s_) * STG_;                              \
    uint32_t bb_ = ab_ + STGA;                                                \
    _Pragma("unroll")                                                         \
    for (int i_ = 0; i_ < 2; i_++) {                                          \
        int idx_ = tid + i_*256; int r_ = idx_ >> 2; int c_ = idx_ & 3;       \
        cp16s(ab_ + r_*ROWB + c_*16, A + (size_t)(bm+r_)*K + (kt_)*GBK + c_*8); \
    }                                                                         \
    _Pragma("unroll")                                                         \
    for (int i_ = 0; i_ < 2; i_++) {                                          \
        int idx_ = tid + i_*256; int r_ = idx_ >> 2; int c_ = idx_ & 3;       \
        cp16s(bb_ + r_*ROWB + c_*16, Wt + (size_t)(bn+r_)*K + (kt_)*GBK + c_*8); \
    }                                                                         \
} while (0)

#define COMPUTE(st_) do {                                                     \
    const uint32_t aB_ = smem + (st_)*STG_ + (uint32_t)(wm)*ROWB + aLane;     \
    const uint32_t bB_ = smem + (st_)*STG_ + STGA + (uint32_t)(wn)*ROWB + bLane; \
    _Pragma("unroll")                                                         \
    for (int ks = 0; ks < 2; ++ks) {                                          \
        uint32_t af[4][4]; uint32_t bf[4][2];                                 \
        _Pragma("unroll")                                                     \
        for (int mt = 0; mt < 4; ++mt)                                        \
            ldsm4(af[mt][0], af[mt][1], af[mt][2], af[mt][3],                 \
                  aB_ + mt*16*ROWB + ks*32);                                  \
        _Pragma("unroll")                                                     \
        for (int np = 0; np < 2; ++np)                                        \
            ldsm4(bf[2*np][0], bf[2*np][1], bf[2*np+1][0], bf[2*np+1][1],     \
                  bB_ + np*16*ROWB + ks*32);                                  \
        _Pragma("unroll")                                                     \
        for (int mt = 0; mt < 4; ++mt)                                        \
            _Pragma("unroll")                                                 \
            for (int nt = 0; nt < 4; ++nt)                                    \
                mma_f16(acc[mt][nt], af[mt], bf[nt]);                         \
    }                                                                         \
} while (0)

template<int EPI>
__global__ void __launch_bounds__(256, 2) gemm_f16_kernel(
    const __half* __restrict__ A, const __half* __restrict__ Wt,
    int K, int N, int nbn, int ntiles,
    const float* __restrict__ px,   // EPI0: x ; EPI1/2: X1
    const float* __restrict__ pxn,  // EPI2: XN (fp32)
    const float* __restrict__ m0,   // tmk / cmk / cmr
    const float* __restrict__ m1,   // tmv
    const float* __restrict__ m2,   // tmr
    float* __restrict__ o0, float* __restrict__ o1, float* __restrict__ o2)
{
    extern __shared__ char dsm[];

    const int tid  = threadIdx.x;
    const int lane = tid & 31;
    const int w    = tid >> 5;
    const int gq   = lane >> 2;
    const int t4   = lane & 3;
    const int wm   = (w & 1) * 64;      // 2x4 warp grid: 64(M) x 32(N) tiles
    const int wn   = (w >> 1) * 32;
    const uint32_t smem = (uint32_t)__cvta_generic_to_shared(dsm);

    // ldmatrix lane address components
    const uint32_t aLane = (uint32_t)(lane & 15) * ROWB + (uint32_t)(lane >> 4) * 16;
    const uint32_t bLane = ((uint32_t)(lane & 7) + (uint32_t)(lane >> 4) * 8) * ROWB
                         + (uint32_t)((lane >> 3) & 1) * 16;

    const int ntk = K / GBK;

    for (int tile = blockIdx.x; tile < ntiles; tile += NCTA) {
        const int bm = (tile / nbn) * 128;
        const int bn = (tile - (tile / nbn) * nbn) * BN;

        float acc[4][4][4];
        #pragma unroll
        for (int i = 0; i < 4; i++)
            #pragma unroll
            for (int j = 0; j < 4; j++)
                #pragma unroll
                for (int q = 0; q < 4; q++) acc[i][j][q] = 0.0f;

        __syncthreads();              // smem stages free for reuse
        LOADSTAGE(0, 0); CP_COMMIT();
        LOADSTAGE(1, 1); CP_COMMIT();
        LOADSTAGE(2, 2); CP_COMMIT();

        for (int kt = 0; kt < ntk; ++kt) {
            CP_WAIT(2);
            __syncthreads();
            const int lt = kt + 3;
            if (lt < ntk) {
                LOADSTAGE(lt & 3, lt);
            }
            CP_COMMIT();
            COMPUTE(kt & 3);
        }

        // ---------------- fused epilogue ----------------
        #pragma unroll
        for (int mt = 0; mt < 4; ++mt) {
            #pragma unroll
            for (int h = 0; h < 2; ++h) {
                const int m = bm + wm + mt*16 + gq + h*8;
                const int t = m & (TT - 1);
                int pm;
                if (EPI == 0) pm = (t == 0) ? m : (m - 1);              // repeat first
                else          pm = (t == 0) ? (m + (TT - 1)) : (m - 1); // wrap
                #pragma unroll
                for (int nt2 = 0; nt2 < 4; ++nt2) {
                    const int n = bn + wn + nt2*8 + t4*2;
                    const float v0 = acc[mt][nt2][h*2];
                    const float v1 = acc[mt][nt2][h*2 + 1];
                    if (EPI == 0) {
                        const int sec = n >> 10;
                        const int cc  = n & (CCH - 1);
                        const float xp0 = px[(size_t)pm*CCH + cc];
                        const float xp1 = px[(size_t)pm*CCH + cc + 1];
                        float* dst; const float* mk;
                        if (sec == 0)      { dst = o0; mk = m0; }
                        else if (sec == 1) { dst = o1; mk = m1; }
                        else               { dst = o2; mk = m2; }
                        const float mk0 = mk[cc], mk1 = mk[cc + 1];
                        float r0 = v0 * mk0 + xp0 * (1.0f - mk0);
                        float r1 = v1 * mk1 + xp1 * (1.0f - mk1);
                        if (sec == 2) { r0 = sigmoidf_(r0); r1 = sigmoidf_(r1); }
                        *(float2*)&dst[(size_t)m*CCH + cc] = make_float2(r0, r1);
                    } else if (EPI == 1) {
                        const int cc = n & (CCH - 1);
                        const float xp0 = px[(size_t)pm*CCH + cc];
                        const float xp1 = px[(size_t)pm*CCH + cc + 1];
                        const float mk0 = m0[cc], mk1 = m0[cc + 1];
                        float k0 = fmaxf(v0 * mk0 + xp0 * (1.0f - mk0), 0.0f);
                        float k1 = fmaxf(v1 * mk1 + xp1 * (1.0f - mk1), 0.0f);
                        __half2 hv = __floats2half2_rn(k0 * k0, k1 * k1);
                        *(__half2*)&((__half*)o0)[(size_t)m*N + n] = hv;
                    } else {
                        const float xp0 = px [(size_t)pm*CCH + n];
                        const float xp1 = px [(size_t)pm*CCH + n + 1];
                        const float xn0 = pxn[(size_t)m *CCH + n];
                        const float xn1 = pxn[(size_t)m *CCH + n + 1];
                        const float mk0 = m0[n], mk1 = m0[n + 1];
                        const float rr0 = sigmoidf_(xn0 * mk0 + xp0 * (1.0f - mk0));
                        const float rr1 = sigmoidf_(xn1 * mk1 + xp1 * (1.0f - mk1));
                        const float x0  = px[(size_t)m*CCH + n];
                        const float x1v = px[(size_t)m*CCH + n + 1];
                        *(float2*)&o0[(size_t)m*CCH + n] =
                            make_float2(x0 + rr0 * v0, x1v + rr1 * v1);
                    }
                }
            }
        }
    }
}

// ---------------- launcher ----------------
extern "C" void kernel_launch(void* const* d_in, const int* in_sizes, int n_in,
                              void* d_out, int out_size)
{
    const float* x    = (const float*)d_in[0];
    const float* td   = (const float*)d_in[1];
    const float* tfst = (const float*)d_in[2];
    const float* W_tm = (const float*)d_in[3];
    const float* g1   = (const float*)d_in[4];
    const float* b1   = (const float*)d_in[5];
    const float* tmk  = (const float*)d_in[6];
    const float* tmv  = (const float*)d_in[7];
    const float* tmr  = (const float*)d_in[8];
    const float* W_cm = (const float*)d_in[9];
    const float* W_cp = (const float*)d_in[10];
    const float* g2   = (const float*)d_in[11];
    const float* b2   = (const float*)d_in[12];
    const float* cmk  = (const float*)d_in[13];
    const float* cmr  = (const float*)d_in[14];
    float* out = (float*)d_out;

    __half *ln1h, *XNh, *Hh, *Wtm, *Wcm, *Wcp;
    float *Kb, *Vb, *Rb, *X1, *XN;
    cudaGetSymbolAddress((void**)&ln1h, g_ln1h);
    cudaGetSymbolAddress((void**)&Kb,  g_K);
    cudaGetSymbolAddress((void**)&Vb,  g_V);
    cudaGetSymbolAddress((void**)&Rb,  g_R);
    cudaGetSymbolAddress((void**)&X1,  g_X1);
    cudaGetSymbolAddress((void**)&XN,  g_XN);
    cudaGetSymbolAddress((void**)&XNh, g_XNh);
    cudaGetSymbolAddress((void**)&Hh,  g_Hh);
    cudaGetSymbolAddress((void**)&Wtm, g_Wtm);
    cudaGetSymbolAddress((void**)&Wcm, g_Wcm);
    cudaGetSymbolAddress((void**)&Wcp, g_Wcp);

    static bool attr_done = false;
    if (!attr_done) {
        cudaFuncSetAttribute(gemm_f16_kernel<0>,
            cudaFuncAttributeMaxDynamicSharedMemorySize, SMEM_TOT);
        cudaFuncSetAttribute(gemm_f16_kernel<1>,
            cudaFuncAttributeMaxDynamicSharedMemorySize, SMEM_TOT);
        cudaFuncSetAttribute(gemm_f16_kernel<2>,
            cudaFuncAttributeMaxDynamicSharedMemorySize, SMEM_TOT);
        attr_done = true;
    }

    // 0) transpose + fp16-convert weights: W(K,N) -> Wt(N,K)
    transpose_h<<<dim3(N3/32,  CCH/32), dim3(32,8)>>>(W_tm, Wtm, CCH, N3);
    transpose_h<<<dim3(N4/32,  CCH/32), dim3(32,8)>>>(W_cm, Wcm, CCH, N4);
    transpose_h<<<dim3(CCH/32, N4/32),  dim3(32,8)>>>(W_cp, Wcp, N4, CCH);

    // 1) LN1 -> half
    ln_kernel<<<BT, 256>>>(x, g1, b1, ln1h, nullptr);

    // 2) GEMM1 (16384x1024x3072) + time-mix epilogue -> K,V,R (fp32)
    gemm_f16_kernel<0><<<NCTA, 256, SMEM_TOT>>>(
        ln1h, Wtm, CCH, N3, N3/BN, (N3/BN)*(BT/128),
        x, nullptr, tmk, tmv, tmr, Kb, Vb, Rb);

    // 3) WKV scan + residual -> X1, new_state into d_out tail
    wkv_kernel<<<BB * (CCH/32), 32>>>(td, tfst, Kb, Vb, Rb, x, X1,
                                      out + (size_t)BT * CCH);

    // 4) LN2 -> half (GEMM input) + fp32 (final epilogue)
    ln_kernel<<<BT, 256>>>(X1, g2, b2, XNh, XN);

    // 5) GEMM2 (16384x1024x4096) + channel-mix + relu^2 -> H (half)
    gemm_f16_kernel<1><<<NCTA, 256, SMEM_TOT>>>(
        XNh, Wcm, CCH, N4, N4/BN, (N4/BN)*(BT/128),
        X1, nullptr, cmk, nullptr, nullptr, (float*)Hh, nullptr, nullptr);

    // 6) GEMM3 (16384x4096x1024) + final residual -> d_out
    gemm_f16_kernel<2><<<NCTA, 256, SMEM_TOT>>>(
        Hh, Wcp, N4, CCH, CCH/BN, (CCH/BN)*(BT/128),
        X1, XN, cmr, nullptr, nullptr, out, nullptr, nullptr);
}